// round 15
// baseline (speedup 1.0000x reference)
#include <cuda_runtime.h>
#include <math.h>

// h = W2 @ gelu(W1 @ bp + b1) + b2, broadcast to all 64 batch rows.
// (fmean of time-standardized features is exactly 0 in exact arithmetic;
//  the reference's fmean is fp32 summation noise ~1e-8 -> ~1e-6 rel effect.)
//
// 32 blocks x 256 threads (256 warps) — proven barrier structure:
//   phase 1: warp gw computes g[2gw], g[2gw+1].
//   grid barrier: monotonic acq_rel ticket + acquire-load spin, ONE polling
//   thread per block (no L2 poll-storm).
//   phase 2: warp gw computes output gw = dot(W2[gw,:], g) + b2[gw];
//            W2 row register-prefetched BEFORE the barrier.
//   epilogue: block owns out cols [8*blk, 8*blk+8) for all 64 rows,
//            fully coalesced float2 stores.

#define DIM    256
#define HID    512
#define NBLK   32
#define NTHR   256

__device__ __align__(16) float g_hidden[HID];
__device__ unsigned int        g_ticket;   // zero-init; monotonic across replays

__global__ void __launch_bounds__(NTHR)
fused_mlp_kernel(const float* __restrict__ bp,
                 const float* __restrict__ W1,
                 const float* __restrict__ b1,
                 const float* __restrict__ W2,
                 const float* __restrict__ b2,
                 float* __restrict__ out)
{
    __shared__ __align__(16) float s_res[8];

    const int warp = threadIdx.x >> 5;              // 0..7
    const int lane = threadIdx.x & 31;
    const int gw   = blockIdx.x * 8 + warp;         // 0..255
    const int r0   = gw * 2;                        // phase-1 rows r0, r0+1
    const int ow   = gw;                            // phase-2 output index

    // ---- Phase-1 loads first (they gate the barrier) ----
    const float4* vb = reinterpret_cast<const float4*>(bp);
    float4 xp0 = __ldg(&vb[lane]);
    float4 xp1 = __ldg(&vb[lane + 32]);
    const float4* rowA = reinterpret_cast<const float4*>(W1 + r0 * DIM);
    const float4* rowB = reinterpret_cast<const float4*>(W1 + (r0 + 1) * DIM);
    float4 a0 = __ldg(&rowA[lane]);
    float4 a1 = __ldg(&rowA[lane + 32]);
    float4 c0 = __ldg(&rowB[lane]);
    float4 c1 = __ldg(&rowB[lane + 32]);
    float  b1a = __ldg(&b1[r0]);
    float  b1b = __ldg(&b1[r0 + 1]);

    // ---- Prefetch phase-2 operands (consumed only after the barrier) ----
    float4 w2r[4];
    const float4* row2 = reinterpret_cast<const float4*>(W2 + ow * HID);
#pragma unroll
    for (int i = 0; i < 4; ++i) w2r[i] = __ldg(&row2[lane + 32 * i]);
    float b2v = __ldg(&b2[ow]);

    // ---- Phase 1: two dots + GELU; lane 0 stores float2 ----
    {
        float acc0 = a0.x * xp0.x + a0.y * xp0.y + a0.z * xp0.z + a0.w * xp0.w
                   + a1.x * xp1.x + a1.y * xp1.y + a1.z * xp1.z + a1.w * xp1.w;
        float acc1 = c0.x * xp0.x + c0.y * xp0.y + c0.z * xp0.z + c0.w * xp0.w
                   + c1.x * xp1.x + c1.y * xp1.y + c1.z * xp1.z + c1.w * xp1.w;
#pragma unroll
        for (int off = 16; off > 0; off >>= 1) {
            acc0 += __shfl_xor_sync(0xffffffffu, acc0, off);
            acc1 += __shfl_xor_sync(0xffffffffu, acc1, off);
        }
        if (lane == 0) {
            float x0 = acc0 + b1a;
            float x1 = acc1 + b1b;
            // exact GELU (approximate=False): 0.5*x*(1+erf(x/sqrt(2)))
            float g0 = 0.5f * x0 * (1.0f + erff(x0 * 0.7071067811865475f));
            float g1 = 0.5f * x1 * (1.0f + erff(x1 * 0.7071067811865475f));
            *reinterpret_cast<float2*>(&g_hidden[r0]) = make_float2(g0, g1);
        }
    }

    // ---- Grid barrier: acq_rel arrival, acquire spin (one thread/block) ----
    __syncthreads();                      // block's g stores program-ordered
    if (threadIdx.x == 0) {
        unsigned int* tick = &g_ticket;
        unsigned int t;
        asm volatile("atom.acq_rel.gpu.global.add.u32 %0, [%1], 1;"
                     : "=r"(t) : "l"(tick) : "memory");
        t += 1u;
        unsigned int target = ((t + NBLK - 1u) / NBLK) * NBLK;  // this replay's goal
        unsigned int v;
        do {
            asm volatile("ld.acquire.gpu.global.u32 %0, [%1];"
                         : "=r"(v) : "l"(tick) : "memory");
        } while ((int)(v - target) < 0);
    }
    __syncthreads();                      // composes acquire block-wide

    // ---- Phase 2: dot(W2[ow,:], g) + b2 (g is L2-hot) ----
    {
        const float4* vg = reinterpret_cast<const float4*>(g_hidden);
        float acc = 0.0f;
#pragma unroll
        for (int i = 0; i < 4; ++i) {
            float4 x = vg[lane + 32 * i];
            acc += w2r[i].x * x.x + w2r[i].y * x.y
                 + w2r[i].z * x.z + w2r[i].w * x.w;
        }
#pragma unroll
        for (int off = 16; off > 0; off >>= 1)
            acc += __shfl_xor_sync(0xffffffffu, acc, off);
        if (lane == 0) s_res[warp] = acc + b2v;
    }
    __syncthreads();

    // ---- Coalesced broadcast: block owns cols [blk*8, blk*8+8) of all 64 rows.
    // thread t: row r = t>>2, pair p = t&3 -> float2 at out[r*256 + blk*8 + 2p].
    {
        int r = threadIdx.x >> 2;
        int p = threadIdx.x & 3;
        float2 v = make_float2(s_res[2 * p], s_res[2 * p + 1]);
        float2* dst = reinterpret_cast<float2*>(out + r * DIM + blockIdx.x * 8 + 2 * p);
        *dst = v;
    }
}

// ---------------------------------------------------------------------------
extern "C" void kernel_launch(void* const* d_in, const int* in_sizes, int n_in,
                              void* d_out, int out_size)
{
    // 0..4: market arrays (unused). Locate Wp (1280 elems); params follow.
    int pi = 5;
    for (int i = 0; i < n_in; ++i)
        if (in_sizes[i] == 1280) { pi = i; break; }

    const float* bp = (const float*)d_in[pi + 1];
    const float* W1 = (const float*)d_in[pi + 2];
    const float* b1 = (const float*)d_in[pi + 3];
    const float* W2 = (const float*)d_in[pi + 4];
    const float* b2 = (const float*)d_in[pi + 5];
    float* out = (float*)d_out;

    fused_mlp_kernel<<<NBLK, NTHR>>>(bp, W1, b1, W2, b2, out);
}

// round 16
// speedup vs baseline: 1.3592x; 1.3592x over previous
#include <cuda_runtime.h>
#include <math.h>

// h = W2 @ gelu(W1 @ bp + b1) + b2, broadcast to all 64 batch rows.
// (fmean of time-standardized features is exactly 0 in exact arithmetic;
//  the reference's fmean is fp32 summation noise ~1e-8 -> ~1e-6 rel effect.)
//
// 32 blocks x 256 threads (256 warps) — proven barrier structure:
//   phase 1: warp gw computes g[2gw], g[2gw+1].
//   grid barrier: monotonic acq_rel ticket + acquire-load spin, ONE polling
//   thread per block (no L2 poll-storm).
//   phase 2: warp gw computes output gw = dot(W2[gw,:], g) + b2[gw];
//            W2 row register-prefetched BEFORE the barrier.
//   epilogue: block owns out cols [8*blk, 8*blk+8) for all 64 rows,
//            fully coalesced float2 stores.

#define DIM    256
#define HID    512
#define NBLK   32
#define NTHR   256

__device__ __align__(16) float g_hidden[HID];
__device__ unsigned int        g_ticket;   // zero-init; monotonic across replays

__global__ void __launch_bounds__(NTHR)
fused_mlp_kernel(const float* __restrict__ bp,
                 const float* __restrict__ W1,
                 const float* __restrict__ b1,
                 const float* __restrict__ W2,
                 const float* __restrict__ b2,
                 float* __restrict__ out)
{
    __shared__ __align__(16) float s_res[8];

    const int warp = threadIdx.x >> 5;              // 0..7
    const int lane = threadIdx.x & 31;
    const int gw   = blockIdx.x * 8 + warp;         // 0..255
    const int r0   = gw * 2;                        // phase-1 rows r0, r0+1
    const int ow   = gw;                            // phase-2 output index

    // ---- Phase-1 loads first (they gate the barrier) ----
    const float4* vb = reinterpret_cast<const float4*>(bp);
    float4 xp0 = __ldg(&vb[lane]);
    float4 xp1 = __ldg(&vb[lane + 32]);
    const float4* rowA = reinterpret_cast<const float4*>(W1 + r0 * DIM);
    const float4* rowB = reinterpret_cast<const float4*>(W1 + (r0 + 1) * DIM);
    float4 a0 = __ldg(&rowA[lane]);
    float4 a1 = __ldg(&rowA[lane + 32]);
    float4 c0 = __ldg(&rowB[lane]);
    float4 c1 = __ldg(&rowB[lane + 32]);
    float  b1a = __ldg(&b1[r0]);
    float  b1b = __ldg(&b1[r0 + 1]);

    // ---- Prefetch phase-2 operands (consumed only after the barrier) ----
    float4 w2r[4];
    const float4* row2 = reinterpret_cast<const float4*>(W2 + ow * HID);
#pragma unroll
    for (int i = 0; i < 4; ++i) w2r[i] = __ldg(&row2[lane + 32 * i]);
    float b2v = __ldg(&b2[ow]);

    // ---- Phase 1: two dots + GELU; lane 0 stores float2 ----
    {
        float acc0 = a0.x * xp0.x + a0.y * xp0.y + a0.z * xp0.z + a0.w * xp0.w
                   + a1.x * xp1.x + a1.y * xp1.y + a1.z * xp1.z + a1.w * xp1.w;
        float acc1 = c0.x * xp0.x + c0.y * xp0.y + c0.z * xp0.z + c0.w * xp0.w
                   + c1.x * xp1.x + c1.y * xp1.y + c1.z * xp1.z + c1.w * xp1.w;
#pragma unroll
        for (int off = 16; off > 0; off >>= 1) {
            acc0 += __shfl_xor_sync(0xffffffffu, acc0, off);
            acc1 += __shfl_xor_sync(0xffffffffu, acc1, off);
        }
        if (lane == 0) {
            float x0 = acc0 + b1a;
            float x1 = acc1 + b1b;
            // exact GELU (approximate=False): 0.5*x*(1+erf(x/sqrt(2)))
            float g0 = 0.5f * x0 * (1.0f + erff(x0 * 0.7071067811865475f));
            float g1 = 0.5f * x1 * (1.0f + erff(x1 * 0.7071067811865475f));
            *reinterpret_cast<float2*>(&g_hidden[r0]) = make_float2(g0, g1);
        }
    }

    // ---- Grid barrier: acq_rel arrival, acquire spin (one thread/block) ----
    __syncthreads();                      // block's g stores program-ordered
    if (threadIdx.x == 0) {
        unsigned int* tick = &g_ticket;
        unsigned int t;
        asm volatile("atom.acq_rel.gpu.global.add.u32 %0, [%1], 1;"
                     : "=r"(t) : "l"(tick) : "memory");
        t += 1u;
        unsigned int target = ((t + NBLK - 1u) / NBLK) * NBLK;  // this replay's goal
        unsigned int v;
        do {
            asm volatile("ld.acquire.gpu.global.u32 %0, [%1];"
                         : "=r"(v) : "l"(tick) : "memory");
        } while ((int)(v - target) < 0);
    }
    __syncthreads();                      // composes acquire block-wide

    // ---- Phase 2: dot(W2[ow,:], g) + b2 (g is L2-hot) ----
    {
        const float4* vg = reinterpret_cast<const float4*>(g_hidden);
        float acc = 0.0f;
#pragma unroll
        for (int i = 0; i < 4; ++i) {
            float4 x = vg[lane + 32 * i];
            acc += w2r[i].x * x.x + w2r[i].y * x.y
                 + w2r[i].z * x.z + w2r[i].w * x.w;
        }
#pragma unroll
        for (int off = 16; off > 0; off >>= 1)
            acc += __shfl_xor_sync(0xffffffffu, acc, off);
        if (lane == 0) s_res[warp] = acc + b2v;
    }
    __syncthreads();

    // ---- Coalesced broadcast: block owns cols [blk*8, blk*8+8) of all 64 rows.
    // thread t: row r = t>>2, pair p = t&3 -> float2 at out[r*256 + blk*8 + 2p].
    {
        int r = threadIdx.x >> 2;
        int p = threadIdx.x & 3;
        float2 v = make_float2(s_res[2 * p], s_res[2 * p + 1]);
        float2* dst = reinterpret_cast<float2*>(out + r * DIM + blockIdx.x * 8 + 2 * p);
        *dst = v;
    }
}

// ---------------------------------------------------------------------------
extern "C" void kernel_launch(void* const* d_in, const int* in_sizes, int n_in,
                              void* d_out, int out_size)
{
    // 0..4: market arrays (unused). Locate Wp (1280 elems); params follow.
    int pi = 5;
    for (int i = 0; i < n_in; ++i)
        if (in_sizes[i] == 1280) { pi = i; break; }

    const float* bp = (const float*)d_in[pi + 1];
    const float* W1 = (const float*)d_in[pi + 2];
    const float* b1 = (const float*)d_in[pi + 3];
    const float* W2 = (const float*)d_in[pi + 4];
    const float* b2 = (const float*)d_in[pi + 5];
    float* out = (float*)d_out;

    fused_mlp_kernel<<<NBLK, NTHR>>>(bp, W1, b1, W2, b2, out);
}